// round 11
// baseline (speedup 1.0000x reference)
#include <cuda_runtime.h>
#include <cuda_fp16.h>
#include <cstdint>

// Correlation cost volume via single-pass fp16 tensor MMA (fp32 accumulate).
//   out[b,i,h,x] = (1/128) * sum_c L[b,c,h,x] * R[b,c,h,x-i],  x>=i, else 0
// b=8, c=128, h=96, w=320, D=48.
//
// R11: 3-stage smem ring. Producer order inside each iteration is
//   stage(k+1) [regs are one full iteration old -> no scoreboard stall]
//   loads(k+2) [LDGs get >= one iteration of flight time]
//   domma(k)
// which removes the exposed DRAM latency R10 paid at stage().
// Skeleton otherwise identical to R10: TM=160, NT=320 (10 warps, m16 each),
// 32-ch chunks, pitch-64 swizzle, bounce epilogue.

namespace {
constexpr int kB = 8, kC = 128, kH = 96, kW = 320, kD = 48;
constexpr int CHW = kH * kW;            // 30720
constexpr int TM = 160;                 // x per CTA tile
constexpr int TN = TM + kD;             // 208 x' rows staged
constexpr int NT = 320;                 // 10 warps; warp wid owns m16 tile
constexpr int NCHUNK = 4;               // 32 channels per chunk

// row = 64 B (32 fp16) per chunk
constexpr int OFF_A = 0;                // 160*64 = 10240
constexpr int OFF_B = TM * 64;          // 10240; B: 208*64 = 13312
constexpr int BUFB  = OFF_B + TN * 64;  // 23552
constexpr int BNC_PITCH = 81;           // floats per bounce row
constexpr int SMEM_TOTAL = 3 * BUFB;    // 70656 > bounce 51840 (overlays)
}

__device__ __forceinline__ uint32_t smem_u32(const void* p) {
    uint32_t a;
    asm("{ .reg .u64 t; cvta.to.shared.u64 t, %1; cvt.u32.u64 %0, t; }" : "=r"(a) : "l"(p));
    return a;
}
__device__ __forceinline__ void ldsm_x4(uint32_t* r, uint32_t addr) {
    asm volatile("ldmatrix.sync.aligned.m8n8.x4.shared.b16 {%0,%1,%2,%3}, [%4];"
                 : "=r"(r[0]), "=r"(r[1]), "=r"(r[2]), "=r"(r[3]) : "r"(addr));
}
__device__ __forceinline__ void mma_f16(float* d, const uint32_t* a, const uint32_t* b) {
    asm volatile(
        "mma.sync.aligned.m16n8k16.row.col.f32.f16.f16.f32 "
        "{%0,%1,%2,%3}, {%4,%5,%6,%7}, {%8,%9}, {%0,%1,%2,%3};"
        : "+f"(d[0]), "+f"(d[1]), "+f"(d[2]), "+f"(d[3])
        : "r"(a[0]), "r"(a[1]), "r"(a[2]), "r"(a[3]), "r"(b[0]), "r"(b[1]));
}

// pitch-64 swizzle: 16B line ^= (row>>1)&3 -> any 8 consecutive rows hit 8
// distinct 16B slots per 128B (CF for STS.128 and all ldmatrix phases).
__device__ __forceinline__ uint32_t swoff(uint32_t row, uint32_t line) {
    return row * 64u + ((line ^ ((row >> 1) & 3u)) << 4);
}

extern __shared__ char smem[];

__global__ __launch_bounds__(NT, 2)
void costvol_ring(const float* __restrict__ L, const float* __restrict__ R,
                  float* __restrict__ out) {
    const uint32_t sb = smem_u32(smem);
    const int tid = threadIdx.x;
    const int wid = tid >> 5;
    const int lid = tid & 31;

    const int tile = blockIdx.x;            // 0..1
    const int bh   = blockIdx.y;            // 0..767
    const int b = bh / kH;
    const int h = bh - b * kH;
    const int X = tile * TM;

    // ---- staging slot geometry (per thread, per 32-ch chunk) ----
    // A: 640 slots (160 rows x 4 g8): s0 = tid, s1 = tid+320.
    // B: 832 slots (208 rows x 4 g8): s0 = tid, s1 = tid+320, s2 = tid+640 (tid<192).
    const int g8A   = tid / TM;              // 0 or 1 (slot1 adds +2)
    const int rowAs = tid - g8A * TM;

    const int g8B0 = tid / TN;               // 0 or 1
    const int rowB0 = tid - g8B0 * TN;
    const int g8B1 = (tid + NT) / TN;        // 1, 2 or 3
    const int rowB1 = tid + NT - g8B1 * TN;
    const int rowB2 = tid + 16;              // slot tid+640 -> g8 = 3

    const int xpB0 = X - kD + rowB0;  const bool okB0 = (xpB0 >= 0);
    const int xpB1 = X - kD + rowB1;  const bool okB1 = (xpB1 >= 0);
    const int xpB2 = X - kD + rowB2;  const bool okB2 = (tid < 192) && (xpB2 >= 0);

    const float* Lb = L + ((long)(b * kC) * kH + h) * kW;
    const float* Rb = R + ((long)(b * kC) * kH + h) * kW;
    const float* pA0  = Lb + (long)(8 * g8A) * CHW + X + rowAs;        // g8A
    const float* pA1  = pA0 + (long)16 * CHW;                          // g8A+2
    const float* pB0b = Rb + (long)(8 * g8B0) * CHW + (okB0 ? xpB0 : 0);
    const float* pB1b = Rb + (long)(8 * g8B1) * CHW + (okB1 ? xpB1 : 0);
    const float* pB2b = Rb + (long)(8 * 3)    * CHW + (okB2 ? xpB2 : 0);

    float fA0[8], fA1[8], fB0[8], fB1[8], fB2[8];

    auto loads = [&](int k) {
        const long co = (long)(32 * k) * CHW;
#pragma unroll
        for (int j = 0; j < 8; j++) {
            fA0[j] = pA0[co + j * CHW];
            fA1[j] = pA1[co + j * CHW];
            fB0[j] = okB0 ? pB0b[co + j * CHW] : 0.f;
            fB1[j] = okB1 ? pB1b[co + j * CHW] : 0.f;
            fB2[j] = okB2 ? pB2b[co + j * CHW] : 0.f;
        }
    };

    auto cvt_store = [&](const float* f, int base_off, int row, int g8) {
        __half2 p0 = __floats2half2_rn(f[0], f[1]);
        __half2 p1 = __floats2half2_rn(f[2], f[3]);
        __half2 p2 = __floats2half2_rn(f[4], f[5]);
        __half2 p3 = __floats2half2_rn(f[6], f[7]);
        uint4 v;
        v.x = *reinterpret_cast<uint32_t*>(&p0);
        v.y = *reinterpret_cast<uint32_t*>(&p1);
        v.z = *reinterpret_cast<uint32_t*>(&p2);
        v.w = *reinterpret_cast<uint32_t*>(&p3);
        *reinterpret_cast<uint4*>(smem + base_off + swoff((uint32_t)row, (uint32_t)g8)) = v;
    };

    auto stage = [&](int buf) {
        const int bo = buf * BUFB;
        cvt_store(fA0, bo + OFF_A, rowAs, g8A);
        cvt_store(fA1, bo + OFF_A, rowAs, g8A + 2);
        cvt_store(fB0, bo + OFF_B, rowB0, g8B0);
        cvt_store(fB1, bo + OFF_B, rowB1, g8B1);
        if (tid < 192) cvt_store(fB2, bo + OFF_B, rowB2, 3);
    };

    // ---- consumer: warp wid owns m rows [16wid,16wid+16), 64-row B window
    float acc[8][4];
#pragma unroll
    for (int j = 0; j < 8; j++)
#pragma unroll
        for (int q = 0; q < 4; q++) acc[j][q] = 0.f;

    const uint32_t rowA = 16u * wid + (lid & 15);
    const uint32_t aHalf = (uint32_t)(lid >> 4);
    const uint32_t bRow  = 8u * (uint32_t)(lid >> 4) + (lid & 7);
    const uint32_t bHalf = (uint32_t)((lid >> 3) & 1);

    auto domma = [&](int buf) {
        const uint32_t base = sb + buf * BUFB;
#pragma unroll
        for (int ks = 0; ks < 2; ks++) {
            uint32_t a4[4];
            ldsm_x4(a4, base + OFF_A + swoff(rowA, 2u * ks + aHalf));
#pragma unroll
            for (int jp = 0; jp < 4; jp++) {
                uint32_t b4[4];
                ldsm_x4(b4, base + OFF_B
                            + swoff(16u * wid + 16u * jp + bRow, 2u * ks + bHalf));
                mma_f16(acc[2 * jp],     a4, b4);
                mma_f16(acc[2 * jp + 1], a4, b4 + 2);
            }
        }
    };

    // ---- 3-stage ring pipeline ----
    // iter k: stage(k+1) (regs one iteration old -> no stall),
    //         loads(k+2) (a full iteration of flight time), domma(k), sync.
    loads(0);
    stage(0);                   // one-time stall on loads(0)
    loads(1);
    __syncthreads();
#pragma unroll
    for (int k = 0; k < NCHUNK; k++) {
        if (k + 1 < NCHUNK) stage((k + 1) % 3);
        if (k + 2 < NCHUNK) loads(k + 2);
        domma(k % 3);
        __syncthreads();
    }

    // ---- acc -> bounce (scaled): warp wid rows [16wid,16wid+16), 64 cols ----
    {
        float* bnc = reinterpret_cast<float*>(smem);
        const float sc = 1.0f / (float)kC;
        const int q = lid >> 2;
        const int e = lid & 3;
        const int m0 = 16 * wid + q;
#pragma unroll
        for (int j = 0; j < 8; j++) {
            const int col = 8 * j + 2 * e;
            bnc[m0 * BNC_PITCH + col]           = acc[j][0] * sc;
            bnc[m0 * BNC_PITCH + col + 1]       = acc[j][1] * sc;
            bnc[(m0 + 8) * BNC_PITCH + col]     = acc[j][2] * sc;
            bnc[(m0 + 8) * BNC_PITCH + col + 1] = acc[j][3] * sc;
        }
    }
    __syncthreads();

    // ---- out[b,i,h,X+xl] = bounce[xl][(xl&15) + 48 - i], coalesced in x ----
    {
        const int half = tid / TM;               // 0 or 1
        const int xl   = tid - half * TM;        // 0..159
        const float* bnr = reinterpret_cast<const float*>(smem)
                         + xl * BNC_PITCH + (xl & 15) + 48;
        float* ob = out + (long)(b * kD) * CHW + h * kW + X + xl;
#pragma unroll
        for (int it = 0; it < 24; it++) {
            const int i = 2 * it + half;
            ob[(long)i * CHW] = bnr[-i];
        }
    }
}

extern "C" void kernel_launch(void* const* d_in, const int* in_sizes, int n_in,
                              void* d_out, int out_size) {
    const float* L = (const float*)d_in[0];
    const float* R = (const float*)d_in[1];
    float* out = (float*)d_out;

    cudaFuncSetAttribute(costvol_ring,
                         cudaFuncAttributeMaxDynamicSharedMemorySize, SMEM_TOTAL);

    dim3 grid(kW / TM, kB * kH);   // (2, 768) = 1536 CTAs
    costvol_ring<<<grid, NT, SMEM_TOTAL>>>(L, R, out);
}

// round 12
// speedup vs baseline: 1.3406x; 1.3406x over previous
#include <cuda_runtime.h>
#include <cuda_fp16.h>
#include <cstdint>

// Correlation cost volume via single-pass fp16 tensor MMA (fp32 accumulate).
//   out[b,i,h,x] = (1/128) * sum_c L[b,c,h,x] * R[b,c,h,x-i],  x>=i, else 0
// b=8, c=128, h=96, w=320, D=48.
//
// R12 = R10 (best known: TM=160, NT=320, 32-ch chunks, double buffer,
// register prefetch of chunk k+1 across MMA(k)) + prefetch.global.L2 of
// chunk k+2 issued one full iteration ahead, so the chunk-(k+1) LDGs hit L2
// (~250 cyc) instead of DRAM (>1000 cyc under load) and fit inside the MMA
// window. Prefetch is registerless/scoreboard-free; ~1.4 instr/thread/iter.

namespace {
constexpr int kB = 8, kC = 128, kH = 96, kW = 320, kD = 48;
constexpr int CHW = kH * kW;            // 30720
constexpr int TM = 160;                 // x per CTA tile
constexpr int TN = TM + kD;             // 208 x' rows staged
constexpr int NT = 320;                 // 10 warps; warp wid owns m16 tile
constexpr int NCHUNK = 4;               // 32 channels per chunk

// row = 64 B (32 fp16) per chunk
constexpr int OFF_A = 0;                // 160*64 = 10240
constexpr int OFF_B = TM * 64;          // 10240; B: 208*64 = 13312
constexpr int BUFB  = OFF_B + TN * 64;  // 23552
constexpr int BNC_PITCH = 81;           // floats per bounce row
constexpr int SMEM_TOTAL = TM * BNC_PITCH * 4;   // 51840 > 2*BUFB (47104)

// prefetch slots: 32 channels x (6 A-lines + 8 B-lines) = 448 x 128B
constexpr int PF_SLOTS = 448;
}

__device__ __forceinline__ uint32_t smem_u32(const void* p) {
    uint32_t a;
    asm("{ .reg .u64 t; cvta.to.shared.u64 t, %1; cvt.u32.u64 %0, t; }" : "=r"(a) : "l"(p));
    return a;
}
__device__ __forceinline__ void ldsm_x4(uint32_t* r, uint32_t addr) {
    asm volatile("ldmatrix.sync.aligned.m8n8.x4.shared.b16 {%0,%1,%2,%3}, [%4];"
                 : "=r"(r[0]), "=r"(r[1]), "=r"(r[2]), "=r"(r[3]) : "r"(addr));
}
__device__ __forceinline__ void mma_f16(float* d, const uint32_t* a, const uint32_t* b) {
    asm volatile(
        "mma.sync.aligned.m16n8k16.row.col.f32.f16.f16.f32 "
        "{%0,%1,%2,%3}, {%4,%5,%6,%7}, {%8,%9}, {%0,%1,%2,%3};"
        : "+f"(d[0]), "+f"(d[1]), "+f"(d[2]), "+f"(d[3])
        : "r"(a[0]), "r"(a[1]), "r"(a[2]), "r"(a[3]), "r"(b[0]), "r"(b[1]));
}
__device__ __forceinline__ void pf_l2(const char* p) {
    asm volatile("prefetch.global.L2 [%0];" :: "l"(p));
}

// pitch-64 swizzle: 16B line ^= (row>>1)&3 -> any 8 consecutive rows hit 8
// distinct 16B slots per 128B (CF for STS.128 and all ldmatrix phases).
__device__ __forceinline__ uint32_t swoff(uint32_t row, uint32_t line) {
    return row * 64u + ((line ^ ((row >> 1) & 3u)) << 4);
}

extern __shared__ char smem[];

__global__ __launch_bounds__(NT, 2)
void costvol_pf(const float* __restrict__ L, const float* __restrict__ R,
                float* __restrict__ out) {
    const uint32_t sb = smem_u32(smem);
    const int tid = threadIdx.x;
    const int wid = tid >> 5;
    const int lid = tid & 31;

    const int tile = blockIdx.x;            // 0..1
    const int bh   = blockIdx.y;            // 0..767
    const int b = bh / kH;
    const int h = bh - b * kH;
    const int X = tile * TM;

    // ---- staging slot geometry (per thread, per 32-ch chunk) ----
    const int g8A   = tid / TM;              // 0 or 1 (slot1 adds +2)
    const int rowAs = tid - g8A * TM;

    const int g8B0 = tid / TN;               // 0 or 1
    const int rowB0 = tid - g8B0 * TN;
    const int g8B1 = (tid + NT) / TN;        // 1, 2 or 3
    const int rowB1 = tid + NT - g8B1 * TN;
    const int rowB2 = tid + 16;              // slot tid+640 -> g8 = 3

    const int xpB0 = X - kD + rowB0;  const bool okB0 = (xpB0 >= 0);
    const int xpB1 = X - kD + rowB1;  const bool okB1 = (xpB1 >= 0);
    const int xpB2 = X - kD + rowB2;  const bool okB2 = (tid < 192) && (xpB2 >= 0);

    const float* Lb = L + ((long)(b * kC) * kH + h) * kW;
    const float* Rb = R + ((long)(b * kC) * kH + h) * kW;
    const float* pA0  = Lb + (long)(8 * g8A) * CHW + X + rowAs;        // g8A
    const float* pA1  = pA0 + (long)16 * CHW;                          // g8A+2
    const float* pB0b = Rb + (long)(8 * g8B0) * CHW + (okB0 ? xpB0 : 0);
    const float* pB1b = Rb + (long)(8 * g8B1) * CHW + (okB1 ? xpB1 : 0);
    const float* pB2b = Rb + (long)(8 * 3)    * CHW + (okB2 ? xpB2 : 0);

    // ---- L2-prefetch slot bases (chunk 0; chunk offset is 128B-multiple) ----
    const int xp0 = (X - kD) > 0 ? (X - kD) : 0;
    const char* const pfEndL = (const char*)(L + (long)kB * kC * CHW) - 128;
    const char* const pfEndR = (const char*)(R + (long)kB * kC * CHW) - 128;
    auto mk_slot = [&](int s, const char*& base, const char*& lim) {
        const int cc = s / 14;
        int li = s % 14;
        const char* p;
        if (li < 6) { p = (const char*)(Lb + (long)cc * CHW + X);  lim = pfEndL; }
        else        { p = (const char*)(Rb + (long)cc * CHW + xp0); lim = pfEndR; li -= 6; }
        base = (const char*)((uintptr_t)p & ~(uintptr_t)127) + (long)li * 128;
    };
    const char *pf0b, *pf0e, *pf1b, *pf1e;
    mk_slot(tid, pf0b, pf0e);
    const bool pf1v = (tid + NT) < PF_SLOTS;
    mk_slot(pf1v ? (tid + NT) : 0, pf1b, pf1e);

    auto prefetch = [&](int k) {
        const long cb = (long)(32 * k) * CHW * (long)sizeof(float);  // 128B-mult
        const char* a0 = pf0b + cb; if (a0 > pf0e) a0 = pf0e;
        pf_l2(a0);
        if (pf1v) {
            const char* a1 = pf1b + cb; if (a1 > pf1e) a1 = pf1e;
            pf_l2(a1);
        }
    };

    float fA0[8], fA1[8], fB0[8], fB1[8], fB2[8];

    auto loads = [&](int k) {
        const long co = (long)(32 * k) * CHW;
#pragma unroll
        for (int j = 0; j < 8; j++) {
            fA0[j] = pA0[co + j * CHW];
            fA1[j] = pA1[co + j * CHW];
            fB0[j] = okB0 ? pB0b[co + j * CHW] : 0.f;
            fB1[j] = okB1 ? pB1b[co + j * CHW] : 0.f;
            fB2[j] = okB2 ? pB2b[co + j * CHW] : 0.f;
        }
    };

    auto cvt_store = [&](const float* f, int base_off, int row, int g8) {
        __half2 p0 = __floats2half2_rn(f[0], f[1]);
        __half2 p1 = __floats2half2_rn(f[2], f[3]);
        __half2 p2 = __floats2half2_rn(f[4], f[5]);
        __half2 p3 = __floats2half2_rn(f[6], f[7]);
        uint4 v;
        v.x = *reinterpret_cast<uint32_t*>(&p0);
        v.y = *reinterpret_cast<uint32_t*>(&p1);
        v.z = *reinterpret_cast<uint32_t*>(&p2);
        v.w = *reinterpret_cast<uint32_t*>(&p3);
        *reinterpret_cast<uint4*>(smem + base_off + swoff((uint32_t)row, (uint32_t)g8)) = v;
    };

    auto stage = [&](int buf) {
        const int bo = buf * BUFB;
        cvt_store(fA0, bo + OFF_A, rowAs, g8A);
        cvt_store(fA1, bo + OFF_A, rowAs, g8A + 2);
        cvt_store(fB0, bo + OFF_B, rowB0, g8B0);
        cvt_store(fB1, bo + OFF_B, rowB1, g8B1);
        if (tid < 192) cvt_store(fB2, bo + OFF_B, rowB2, 3);
    };

    // ---- consumer: warp wid owns m rows [16wid,16wid+16), 64-row B window
    float acc[8][4];
#pragma unroll
    for (int j = 0; j < 8; j++)
#pragma unroll
        for (int q = 0; q < 4; q++) acc[j][q] = 0.f;

    const uint32_t rowA = 16u * wid + (lid & 15);
    const uint32_t aHalf = (uint32_t)(lid >> 4);
    const uint32_t bRow  = 8u * (uint32_t)(lid >> 4) + (lid & 7);
    const uint32_t bHalf = (uint32_t)((lid >> 3) & 1);

    auto domma = [&](int buf) {
        const uint32_t base = sb + buf * BUFB;
#pragma unroll
        for (int ks = 0; ks < 2; ks++) {
            uint32_t a4[4];
            ldsm_x4(a4, base + OFF_A + swoff(rowA, 2u * ks + aHalf));
#pragma unroll
            for (int jp = 0; jp < 4; jp++) {
                uint32_t b4[4];
                ldsm_x4(b4, base + OFF_B
                            + swoff(16u * wid + 16u * jp + bRow, 2u * ks + bHalf));
                mma_f16(acc[2 * jp],     a4, b4);
                mma_f16(acc[2 * jp + 1], a4, b4 + 2);
            }
        }
    };

    // ---- pipeline: pf(k+2) one iter ahead; LDG(k+1) (L2 hits) across MMA(k) ----
    prefetch(0);
    prefetch(1);
    loads(0);
    stage(0);
    __syncthreads();
#pragma unroll
    for (int k = 0; k < NCHUNK; k++) {
        if (k + 2 < NCHUNK) prefetch(k + 2);
        if (k + 1 < NCHUNK) loads(k + 1);
        domma(k & 1);
        if (k + 1 < NCHUNK) stage((k + 1) & 1);
        __syncthreads();
    }

    // ---- acc -> bounce (scaled): warp wid rows [16wid,16wid+16), 64 cols ----
    {
        float* bnc = reinterpret_cast<float*>(smem);
        const float sc = 1.0f / (float)kC;
        const int q = lid >> 2;
        const int e = lid & 3;
        const int m0 = 16 * wid + q;
#pragma unroll
        for (int j = 0; j < 8; j++) {
            const int col = 8 * j + 2 * e;
            bnc[m0 * BNC_PITCH + col]           = acc[j][0] * sc;
            bnc[m0 * BNC_PITCH + col + 1]       = acc[j][1] * sc;
            bnc[(m0 + 8) * BNC_PITCH + col]     = acc[j][2] * sc;
            bnc[(m0 + 8) * BNC_PITCH + col + 1] = acc[j][3] * sc;
        }
    }
    __syncthreads();

    // ---- out[b,i,h,X+xl] = bounce[xl][(xl&15) + 48 - i], coalesced in x ----
    {
        const int half = tid / TM;               // 0 or 1
        const int xl   = tid - half * TM;        // 0..159
        const float* bnr = reinterpret_cast<const float*>(smem)
                         + xl * BNC_PITCH + (xl & 15) + 48;
        float* ob = out + (long)(b * kD) * CHW + h * kW + X + xl;
#pragma unroll
        for (int it = 0; it < 24; it++) {
            const int i = 2 * it + half;
            ob[(long)i * CHW] = bnr[-i];
        }
    }
}

extern "C" void kernel_launch(void* const* d_in, const int* in_sizes, int n_in,
                              void* d_out, int out_size) {
    const float* L = (const float*)d_in[0];
    const float* R = (const float*)d_in[1];
    float* out = (float*)d_out;

    cudaFuncSetAttribute(costvol_pf,
                         cudaFuncAttributeMaxDynamicSharedMemorySize, SMEM_TOTAL);

    dim3 grid(kW / TM, kB * kH);   // (2, 768) = 1536 CTAs
    costvol_pf<<<grid, NT, SMEM_TOTAL>>>(L, R, out);
}